// round 15
// baseline (speedup 1.0000x reference)
#include <cuda_runtime.h>
#include <cuda_fp16.h>
#include <cstdint>

#define BATCH 4
#define CH    256
#define NPIX  4096
#define TQ    128
#define TJ    64
#define NTILE (NPIX / TJ)
#define NT_A  256
#define NT    512

// attention operands (written by proj kernels)
__device__ __align__(128) __half  g_Qh[(size_t)BATCH * NPIX * CH];
__device__ __align__(128) __half  g_Kh[(size_t)BATCH * NPIX * CH];
__device__ __align__(128) uint8_t g_Q8h[(size_t)BATCH * NPIX * CH];  // fp8(hi)
__device__ __align__(128) uint8_t g_Q8l[(size_t)BATCH * NPIX * CH];  // fp8(4096*lo)
__device__ __align__(128) uint8_t g_K8h[(size_t)BATCH * NPIX * CH];
__device__ __align__(128) uint8_t g_K8l[(size_t)BATCH * NPIX * CH];
__device__ __align__(128) __half  g_V [(size_t)BATCH * CH * NPIX];   // channel-major fp16

// split inputs for the tensor-core projections
__device__ __align__(128) __half g_x1h[(size_t)BATCH * NPIX * CH];
__device__ __align__(128) __half g_x1l[(size_t)BATCH * NPIX * CH];
__device__ __align__(128) __half g_x2h[(size_t)BATCH * NPIX * CH];
__device__ __align__(128) __half g_x2l[(size_t)BATCH * NPIX * CH];
__device__ __align__(128) __half g_wqh[CH * CH], g_wql[CH * CH];
__device__ __align__(128) __half g_wkh[CH * CH], g_wkl[CH * CH];
__device__ __align__(128) __half g_wvh[CH * CH], g_wvl[CH * CH];

// ---- attn smem layout ----
#define SM_Q    0           // Qh fp16 128 x 512B
#define SM_Q8H  65536       // 128 x 256B
#define SM_Q8L  98304       // 128 x 256B
#define SM_K    131072      // Kh fp16 64 x 512B
#define SM_K8H  163840      // 64 x 256B
#define SM_K8L  180224      // 64 x 256B
#define SM_V    196608      // V 256 x 128B
#define SM_TOT  229376

// ---- proj smem layout ----
#define PSM_X0  0
#define PSM_X1  32768
#define PSM_XL  16384
#define PSM_W0  65536
#define PSM_W1  131072
#define PSM_WL  32768
#define PSM_TOT 196608

#define CP16(dst, src) asm volatile("cp.async.cg.shared.global [%0], [%1], 16;" :: "r"(dst), "l"(src))
#define CP_COMMIT()    asm volatile("cp.async.commit_group;")
#define CP_WAIT_N(n)   asm volatile("cp.async.wait_group %0;" :: "n"(n))

__device__ __forceinline__ uint32_t smem_u32(const void* p) {
    uint32_t a;
    asm("{ .reg .u64 t; cvta.to.shared.u64 t, %1; cvt.u32.u64 %0, t; }" : "=r"(a) : "l"(p));
    return a;
}
__device__ __forceinline__ void ldsm4(uint32_t* r, uint32_t addr) {
    asm volatile("ldmatrix.sync.aligned.m8n8.x4.shared.b16 {%0,%1,%2,%3}, [%4];"
        : "=r"(r[0]), "=r"(r[1]), "=r"(r[2]), "=r"(r[3]) : "r"(addr));
}
__device__ __forceinline__ void mma16816(float* c, const uint32_t* a, uint32_t b0, uint32_t b1) {
    asm volatile(
        "mma.sync.aligned.m16n8k16.row.col.f32.f16.f16.f32 "
        "{%0,%1,%2,%3}, {%4,%5,%6,%7}, {%8,%9}, {%0,%1,%2,%3};"
        : "+f"(c[0]), "+f"(c[1]), "+f"(c[2]), "+f"(c[3])
        : "r"(a[0]), "r"(a[1]), "r"(a[2]), "r"(a[3]), "r"(b0), "r"(b1));
}
__device__ __forceinline__ void mma16832f8(float* c, const uint32_t* a, uint32_t b0, uint32_t b1) {
    asm volatile(
        "mma.sync.aligned.m16n8k32.row.col.f32.e4m3.e4m3.f32 "
        "{%0,%1,%2,%3}, {%4,%5,%6,%7}, {%8,%9}, {%0,%1,%2,%3};"
        : "+f"(c[0]), "+f"(c[1]), "+f"(c[2]), "+f"(c[3])
        : "r"(a[0]), "r"(a[1]), "r"(a[2]), "r"(a[3]), "r"(b0), "r"(b1));
}
__device__ __forceinline__ uint32_t pack_h(__half a, __half b) {
    uint16_t ra = __half_as_ushort(a), rb = __half_as_ushort(b);
    return (uint32_t)ra | ((uint32_t)rb << 16);
}
__device__ __forceinline__ uint32_t packf2(float a, float b) {
    __half2 h = __float22half2_rn(make_float2(a, b));
    return *(uint32_t*)&h;
}
// pack two floats to e4m3 pair: byte0 = e0, byte1 = e1
__device__ __forceinline__ uint16_t pack8(float e0, float e1) {
    uint16_t r;
    asm("cvt.rn.satfinite.e4m3x2.f32 %0, %1, %2;" : "=h"(r) : "f"(e1), "f"(e0));
    return r;
}
__device__ __forceinline__ void hsplit(float v, __half& h, __half& l) {
    h = __float2half_rn(v);
    l = __float2half_rn(v - __half2float(h));
}

// ---------------------------------------------------------------------------
// split + transpose: both x1 and x2 in one launch
// ---------------------------------------------------------------------------
__global__ __launch_bounds__(256) void splitx_kernel(
    const float* __restrict__ x1, const float* __restrict__ x2)
{
    __shared__ float tile[32][33];
    const int which = blockIdx.z >= BATCH ? 1 : 0;
    const int b = blockIdx.z - which * BATCH;
    const float* x = which ? x2 : x1;
    __half* xh = which ? g_x2h : g_x1h;
    __half* xl = which ? g_x2l : g_x1l;
    const int c0 = blockIdx.y * 32, p0 = blockIdx.x * 32;
    const int tx = threadIdx.x, ty = threadIdx.y;

    const float* xb = x + ((size_t)b * CH + c0) * NPIX + p0;
#pragma unroll
    for (int i = 0; i < 4; ++i)
        tile[ty + 8 * i][tx] = xb[(size_t)(ty + 8 * i) * NPIX + tx];
    __syncthreads();

    __half* oh = xh + ((size_t)b * NPIX + p0) * CH + c0;
    __half* ol = xl + ((size_t)b * NPIX + p0) * CH + c0;
#pragma unroll
    for (int i = 0; i < 4; ++i) {
        float v = tile[tx][ty + 8 * i];
        __half h, l; hsplit(v, h, l);
        oh[(size_t)(ty + 8 * i) * CH + tx] = h;
        ol[(size_t)(ty + 8 * i) * CH + tx] = l;
    }
}

__global__ __launch_bounds__(512) void splitw_kernel(
    const float* __restrict__ qw, const float* __restrict__ kw,
    const float* __restrict__ vw)
{
    const int per = CH * CH / 512;
    const int which = blockIdx.x / per;
    const int i = (blockIdx.x - which * per) * 512 + threadIdx.x;
    const float* w = (which == 0) ? qw : (which == 1) ? kw : vw;
    __half* wh = (which == 0) ? g_wqh : (which == 1) ? g_wkh : g_wvh;
    __half* wl = (which == 0) ? g_wql : (which == 1) ? g_wkl : g_wvl;
    float v = w[i];
    __half h, l; hsplit(v, h, l);
    wh[i] = h; wl[i] = l;
}

// ---------------------------------------------------------------------------
// Tensor-core projection GEMM — Q/K/V in ONE launch (which = blockIdx.y).
// Q/K epilogue: fp16 hi + fp8(h) + fp8(4096*l).
// ---------------------------------------------------------------------------
__device__ __forceinline__ void proj_load_chunk(
    uint32_t sb, uint32_t xoff, uint32_t woff, int cc, int t,
    const __half* xb, const __half* xlb, const __half* wh, const __half* wl)
{
    const int c0 = cc * 64;
#pragma unroll
    for (int i = 0; i < 2; ++i) {
        int idx = t + NT * i;
        int row = idx >> 3, c8 = idx & 7;
        uint32_t off = (uint32_t)row * 128u + (uint32_t)((c8 ^ (row & 7)) << 4);
        CP16(sb + xoff + off,          xb  + (size_t)row * CH + c0 + c8 * 8);
        CP16(sb + xoff + PSM_XL + off, xlb + (size_t)row * CH + c0 + c8 * 8);
    }
#pragma unroll
    for (int i = 0; i < 4; ++i) {
        int idx = t + NT * i;
        int row = idx >> 3, c8 = idx & 7;
        uint32_t off = (uint32_t)row * 128u + (uint32_t)((c8 ^ (row & 7)) << 4);
        CP16(sb + woff + off,          wh + (size_t)row * CH + c0 + c8 * 8);
        CP16(sb + woff + PSM_WL + off, wl + (size_t)row * CH + c0 + c8 * 8);
    }
}

__global__ __launch_bounds__(NT, 1) void projmma_kernel(
    const float* __restrict__ qb, const float* __restrict__ kb,
    const float* __restrict__ vb)
{
    extern __shared__ char smem[];
    const uint32_t sb = smem_u32(smem);
    const int t = threadIdx.x, lane = t & 31, wid = t >> 5;
    const int which = blockIdx.y;
    const int b = blockIdx.z, p0 = blockIdx.x * 128;
    const int pw = wid & 3, ow = wid >> 2;
    const int g = lane >> 2, tig = lane & 3;
    const uint32_t l15 = (uint32_t)(lane & 15), lhi = (uint32_t)(lane >> 4);

    const float* bias = (which == 0) ? qb : (which == 1) ? kb : vb;
    const __half *xh, *xl, *wh, *wl;
    if (which == 0)      { xh = g_x1h; xl = g_x1l; wh = g_wqh; wl = g_wql; }
    else if (which == 1) { xh = g_x2h; xl = g_x2l; wh = g_wkh; wl = g_wkl; }
    else                 { xh = g_x2h; xl = g_x2l; wh = g_wvh; wl = g_wvl; }

    const __half* xb  = xh + ((size_t)b * NPIX + p0) * CH;
    const __half* xlb = xl + ((size_t)b * NPIX + p0) * CH;

    float oacc[2][8][4];
#pragma unroll
    for (int m = 0; m < 2; ++m)
#pragma unroll
        for (int nb = 0; nb < 8; ++nb)
#pragma unroll
            for (int i = 0; i < 4; ++i) oacc[m][nb][i] = 0.f;

    const uint32_t am7 = l15 & 7u;
    const uint32_t aXrow = ((uint32_t)(pw * 32) + l15) * 128u;
    const uint32_t aWrow = ((uint32_t)(ow * 64) + l15) * 128u;

    proj_load_chunk(sb, PSM_X0, PSM_W0, 0, t, xb, xlb, wh, wl);
    CP_COMMIT();

#pragma unroll 1
    for (int cc = 0; cc < 4; ++cc) {
        __syncthreads();
        if (cc + 1 < 4) {
            proj_load_chunk(sb, (cc + 1) & 1 ? PSM_X1 : PSM_X0,
                            (cc + 1) & 1 ? PSM_W1 : PSM_W0, cc + 1, t, xb, xlb, wh, wl);
            CP_COMMIT();
        }
        if (cc + 1 < 4) CP_WAIT_N(1); else CP_WAIT_N(0);
        __syncthreads();

        const uint32_t aXh = sb + ((cc & 1) ? PSM_X1 : PSM_X0) + aXrow;
        const uint32_t aXl = aXh + PSM_XL;
        const uint32_t aWh = sb + ((cc & 1) ? PSM_W1 : PSM_W0) + aWrow;
        const uint32_t aWl = aWh + PSM_WL;

#pragma unroll
        for (int kk = 0; kk < 4; ++kk) {
            const uint32_t kc = (uint32_t)(kk * 2) + lhi;
            const uint32_t ca = (kc ^ am7) << 4;
            uint32_t Ah[2][4], Al[2][4];
            ldsm4(Ah[0], aXh + ca); ldsm4(Ah[1], aXh + 2048u + ca);
            ldsm4(Al[0], aXl + ca); ldsm4(Al[1], aXl + 2048u + ca);
#pragma unroll
            for (int seg = 0; seg < 4; ++seg) {
                uint32_t Bh[4], Bl[4];
                ldsm4(Bh, aWh + (uint32_t)seg * 2048u + ca);
                ldsm4(Bl, aWl + (uint32_t)seg * 2048u + ca);
#pragma unroll
                for (int m = 0; m < 2; ++m)
#pragma unroll
                    for (int h = 0; h < 2; ++h) {
                        float* c = oacc[m][seg * 2 + h];
                        mma16816(c, Ah[m], Bh[h], Bh[h + 2]);
                        mma16816(c, Al[m], Bh[h], Bh[h + 2]);
                        mma16816(c, Ah[m], Bl[h], Bl[h + 2]);
                    }
            }
        }
    }

    if (which < 2) {
        __half*   OH  = which ? g_Kh  : g_Qh;
        uint8_t*  O8H = which ? g_K8h : g_Q8h;
        uint8_t*  O8L = which ? g_K8l : g_Q8l;
#pragma unroll
        for (int m = 0; m < 2; ++m) {
            const int p_lo = p0 + pw * 32 + m * 16 + g;
#pragma unroll
            for (int nb = 0; nb < 8; ++nb) {
                const int o = ow * 64 + nb * 8 + 2 * tig;
                const float b0 = bias[o], b1 = bias[o + 1];
                float v0 = oacc[m][nb][0] + b0, v1 = oacc[m][nb][1] + b1;
                float v2 = oacc[m][nb][2] + b0, v3 = oacc[m][nb][3] + b1;
                __half h0, l0, h1, l1;
                hsplit(v0, h0, l0); hsplit(v1, h1, l1);
                size_t a0 = ((size_t)b * NPIX + p_lo) * CH + o;
                *(uint32_t*)(OH + a0)  = pack_h(h0, h1);
                *(uint16_t*)(O8H + a0) = pack8(__half2float(h0), __half2float(h1));
                *(uint16_t*)(O8L + a0) = pack8(4096.f * __half2float(l0),
                                               4096.f * __half2float(l1));
                hsplit(v2, h0, l0); hsplit(v3, h1, l1);
                size_t a1 = a0 + (size_t)8 * CH;
                *(uint32_t*)(OH + a1)  = pack_h(h0, h1);
                *(uint16_t*)(O8H + a1) = pack8(__half2float(h0), __half2float(h1));
                *(uint16_t*)(O8L + a1) = pack8(4096.f * __half2float(l0),
                                               4096.f * __half2float(l1));
            }
        }
    } else {
        __syncthreads();
#pragma unroll
        for (int m = 0; m < 2; ++m) {
            const int p_lo = pw * 32 + m * 16 + g;
#pragma unroll
            for (int nb = 0; nb < 8; ++nb) {
                const int o = ow * 64 + nb * 8 + 2 * tig;
                const float b0 = bias[o], b1 = bias[o + 1];
                *(__half*)(smem + o * 272 + p_lo * 2)             = __float2half_rn(oacc[m][nb][0] + b0);
                *(__half*)(smem + (o + 1) * 272 + p_lo * 2)       = __float2half_rn(oacc[m][nb][1] + b1);
                *(__half*)(smem + o * 272 + (p_lo + 8) * 2)       = __float2half_rn(oacc[m][nb][2] + b0);
                *(__half*)(smem + (o + 1) * 272 + (p_lo + 8) * 2) = __float2half_rn(oacc[m][nb][3] + b1);
            }
        }
        __syncthreads();
#pragma unroll
        for (int i = 0; i < 8; ++i) {
            int idx = t + NT * i;
            int o = idx & 255, pg = idx >> 8;
            uint4 v = *(uint4*)(smem + o * 272 + pg * 16);
            *(uint4*)(g_V + ((size_t)b * CH + o) * NPIX + p0 + pg * 8) = v;
        }
    }
}

// ---------------------------------------------------------------------------
// Flash-style attention: S = Qh*Kh (fp16) + fp8 cross terms (k32 MMAs).
// P in registers; V(t)/K(t+1) hidden under compute. 256 threads / 8 warps.
// ---------------------------------------------------------------------------
__global__ __launch_bounds__(NT_A, 1) void attn_kernel(
    const float* __restrict__ lnw, const float* __restrict__ lnb,
    float* __restrict__ out)
{
    extern __shared__ char smem[];
    const uint32_t sb = smem_u32(smem);
    const int t = threadIdx.x;
    const int lane = t & 31, wid = t >> 5;
    const int b = blockIdx.y;
    const int p0 = blockIdx.x * TQ;
    const int g = lane >> 2, tig = lane & 3;
    const uint32_t l15 = (uint32_t)(lane & 15), lhi = (uint32_t)(lane >> 4);
    const uint32_t m7 = l15 & 7u;

    const __half*  khb  = g_Kh  + (size_t)b * NPIX * CH;
    const uint8_t* k8hb = g_K8h + (size_t)b * NPIX * CH;
    const uint8_t* k8lb = g_K8l + (size_t)b * NPIX * CH;
    const __half*  vb_  = g_V   + (size_t)b * CH * NPIX;

    // prologue: Qh fp16 + Q8h/Q8l fp8 + K(0), one commit group
    {
        const __half*  qh  = g_Qh  + ((size_t)b * NPIX + p0) * CH;
        const uint8_t* q8h = g_Q8h + ((size_t)b * NPIX + p0) * CH;
        const uint8_t* q8l = g_Q8l + ((size_t)b * NPIX + p0) * CH;
#pragma unroll
        for (int i = 0; i < 16; ++i) {
            int idx = t + NT_A * i;
            int row = idx >> 5, c = idx & 31;
            uint32_t off = (uint32_t)row * 512u + (uint32_t)((c ^ (row & 7)) << 4);
            CP16(sb + SM_Q + off, qh + (size_t)row * CH + c * 8);
        }
#pragma unroll
        for (int i = 0; i < 8; ++i) {
            int idx = t + NT_A * i;
            int row = idx >> 4, c = idx & 15;
            uint32_t off = (uint32_t)row * 256u + (uint32_t)((c ^ (row & 7)) << 4);
            CP16(sb + SM_Q8H + off, q8h + (size_t)row * CH + c * 16);
            CP16(sb + SM_Q8L + off, q8l + (size_t)row * CH + c * 16);
        }
#pragma unroll
        for (int i = 0; i < 8; ++i) {
            int idx = t + NT_A * i;
            int row = idx >> 5, c = idx & 31;
            uint32_t off = (uint32_t)row * 512u + (uint32_t)((c ^ (row & 7)) << 4);
            CP16(sb + SM_K + off, khb + (size_t)row * CH + c * 8);
        }
#pragma unroll
        for (int i = 0; i < 4; ++i) {
            int idx = t + NT_A * i;
            int row = idx >> 4, c = idx & 15;
            uint32_t off = (uint32_t)row * 256u + (uint32_t)((c ^ (row & 7)) << 4);
            CP16(sb + SM_K8H + off, k8hb + (size_t)row * CH + c * 16);
            CP16(sb + SM_K8L + off, k8lb + (size_t)row * CH + c * 16);
        }
        CP_COMMIT();
    }

    float oacc[32][4];
#pragma unroll
    for (int nb = 0; nb < 32; ++nb)
#pragma unroll
        for (int i = 0; i < 4; ++i) oacc[nb][i] = 0.f;

    const uint32_t qrow = (uint32_t)(wid * 16) + l15;
    const uint32_t aQh  = sb + SM_Q   + qrow * 512u;
    const uint32_t aQ8h = sb + SM_Q8H + qrow * 256u;
    const uint32_t aQ8l = sb + SM_Q8L + qrow * 256u;
    const uint32_t aK   = sb + SM_K   + l15 * 512u;
    const uint32_t aK8h = sb + SM_K8H + l15 * 256u;
    const uint32_t aK8l = sb + SM_K8L + l15 * 256u;
    const uint32_t aV   = sb + SM_V   + l15 * 128u;

#pragma unroll 1
    for (int tile = 0; tile < NTILE; ++tile) {
        CP_WAIT_N(0);      // K(t) landed
        __syncthreads();   // K visible; AV(t-1) done -> V region free

        // issue V(t) — lands under S
        {
            const __half* vh = vb_ + (size_t)tile * TJ;
#pragma unroll
            for (int i = 0; i < 8; ++i) {
                int idx = t + NT_A * i;
                int row = idx >> 3, c = idx & 7;
                uint32_t off = (uint32_t)row * 128u + (uint32_t)((c ^ (row & 7)) << 4);
                CP16(sb + SM_V + off, vh + (size_t)row * NPIX + c * 8);
            }
            CP_COMMIT();
        }

        float sacc[8][4];
#pragma unroll
        for (int nb = 0; nb < 8; ++nb)
#pragma unroll
            for (int i = 0; i < 4; ++i) sacc[nb][i] = 0.f;

        // ---- fp8 cross terms: Qh8*(4096*Kl) + (4096*Ql)*Kh8  (k32 MMAs)
#pragma unroll
        for (int kk8 = 0; kk8 < 8; ++kk8) {
            const uint32_t cg = (((uint32_t)(kk8 * 2) + lhi) ^ m7) << 4;
            uint32_t A8h[4], A8l[4];
            ldsm4(A8h, aQ8h + cg);
            ldsm4(A8l, aQ8l + cg);
#pragma unroll
            for (int jb = 0; jb < 4; ++jb) {
                uint32_t B8h[4], B8l[4];
                ldsm4(B8h, aK8h + (uint32_t)jb * 4096u + cg);
                ldsm4(B8l, aK8l + (uint32_t)jb * 4096u + cg);
#pragma unroll
                for (int h = 0; h < 2; ++h) {
                    float* c = sacc[jb * 2 + h];
                    mma16832f8(c, A8h, B8l[h], B8l[h + 2]);
                    mma16832f8(c, A8l, B8h[h], B8h[h + 2]);
                }
            }
        }
        // scale cross terms back by 2^-12
#pragma unroll
        for (int nb = 0; nb < 8; ++nb)
#pragma unroll
            for (int i = 0; i < 4; ++i) sacc[nb][i] *= (1.f / 4096.f);

        // ---- fp16 hh term accumulates on top
#pragma unroll
        for (int k = 0; k < 16; ++k) {
            const uint32_t kc = (uint32_t)(k * 2) + lhi;
            const uint32_t ck = (kc ^ m7) << 4;
            uint32_t Ah[4];
            ldsm4(Ah, aQh + ck);
#pragma unroll
            for (int jb = 0; jb < 4; ++jb) {
                uint32_t Bh[4];
                ldsm4(Bh, aK + (uint32_t)jb * 8192u + ck);
#pragma unroll
                for (int h = 0; h < 2; ++h)
                    mma16816(sacc[jb * 2 + h], Ah, Bh[h], Bh[h + 2]);
            }
        }
        __syncthreads();   // all warps done reading K(t)

        // issue K(t+1) — lands under softmax + AV
        if (tile + 1 < NTILE) {
            const __half*  kh  = khb  + (size_t)(tile + 1) * TJ * CH;
            const uint8_t* k8h = k8hb + (size_t)(tile + 1) * TJ * CH;
            const uint8_t* k8l = k8lb + (size_t)(tile + 1) * TJ * CH;
#pragma unroll
            for (int i = 0; i < 8; ++i) {
                int idx = t + NT_A * i;
                int row = idx >> 5, c = idx & 31;
                uint32_t off = (uint32_t)row * 512u + (uint32_t)((c ^ (row & 7)) << 4);
                CP16(sb + SM_K + off, kh + (size_t)row * CH + c * 8);
            }
#pragma unroll
            for (int i = 0; i < 4; ++i) {
                int idx = t + NT_A * i;
                int row = idx >> 4, c = idx & 15;
                uint32_t off = (uint32_t)row * 256u + (uint32_t)((c ^ (row & 7)) << 4);
                CP16(sb + SM_K8H + off, k8h + (size_t)row * CH + c * 16);
                CP16(sb + SM_K8L + off, k8l + (size_t)row * CH + c * 16);
            }
            CP_COMMIT();
        }

        // ---- warp-local softmax (rows g and g+8)
        float inv0, inv1;
        {
            float mx0 = -1e30f, mx1 = -1e30f;
#pragma unroll
            for (int nb = 0; nb < 8; ++nb) {
                mx0 = fmaxf(mx0, fmaxf(sacc[nb][0], sacc[nb][1]));
                mx1 = fmaxf(mx1, fmaxf(sacc[nb][2], sacc[nb][3]));
            }
            mx0 = fmaxf(mx0, __shfl_xor_sync(0xffffffffu, mx0, 1));
            mx0 = fmaxf(mx0, __shfl_xor_sync(0xffffffffu, mx0, 2));
            mx1 = fmaxf(mx1, __shfl_xor_sync(0xffffffffu, mx1, 1));
            mx1 = fmaxf(mx1, __shfl_xor_sync(0xffffffffu, mx1, 2));
            float s0 = 0.f, s1 = 0.f;
#pragma unroll
            for (int nb = 0; nb < 8; ++nb) {
                float e0 = __expf(sacc[nb][0] - mx0);
                float e1 = __expf(sacc[nb][1] - mx0);
                float e2 = __expf(sacc[nb][2] - mx1);
                float e3 = __expf(sacc[nb][3] - mx1);
                sacc[nb][0] = e0; sacc[nb][1] = e1;
                sacc[nb][2] = e2; sacc[nb][3] = e3;
                s0 += e0 + e1; s1 += e2 + e3;
            }
            s0 += __shfl_xor_sync(0xffffffffu, s0, 1);
            s0 += __shfl_xor_sync(0xffffffffu, s0, 2);
            s1 += __shfl_xor_sync(0xffffffffu, s1, 1);
            s1 += __shfl_xor_sync(0xffffffffu, s1, 2);
            inv0 = __fdividef(1.f, s0);
            inv1 = __fdividef(1.f, s1);
        }

        uint32_t pfrag[4][4];
#pragma unroll
        for (int kk = 0; kk < 4; ++kk) {
            pfrag[kk][0] = packf2(sacc[2 * kk][0] * inv0,     sacc[2 * kk][1] * inv0);
            pfrag[kk][1] = packf2(sacc[2 * kk][2] * inv1,     sacc[2 * kk][3] * inv1);
            pfrag[kk][2] = packf2(sacc[2 * kk + 1][0] * inv0, sacc[2 * kk + 1][1] * inv0);
            pfrag[kk][3] = packf2(sacc[2 * kk + 1][2] * inv1, sacc[2 * kk + 1][3] * inv1);
        }

        if (tile + 1 < NTILE) CP_WAIT_N(1); else CP_WAIT_N(0);   // V(t) landed
        __syncthreads();

        // ---- O += P V (warp tile 16q x 256c)
#pragma unroll
        for (int kk = 0; kk < 4; ++kk) {
            const uint32_t cv = (((uint32_t)(kk * 2) + lhi) ^ m7) << 4;
#pragma unroll
            for (int nbp = 0; nbp < 16; ++nbp) {
                uint32_t Bv[4];
                ldsm4(Bv, aV + (uint32_t)nbp * 2048u + cv);
                mma16816(oacc[nbp * 2],     pfrag[kk], Bv[0], Bv[2]);
                mma16816(oacc[nbp * 2 + 1], pfrag[kk], Bv[1], Bv[3]);
            }
        }
    }

    // ---- fused LayerNorm epilogue
#pragma unroll
    for (int hf = 0; hf < 2; ++hf) {
        float s1 = 0.f, s2 = 0.f;
#pragma unroll
        for (int nb = 0; nb < 32; ++nb) {
            float v0 = oacc[nb][hf * 2], v1 = oacc[nb][hf * 2 + 1];
            s1 += v0 + v1; s2 += v0 * v0 + v1 * v1;
        }
        s1 += __shfl_xor_sync(0xffffffffu, s1, 1);
        s1 += __shfl_xor_sync(0xffffffffu, s1, 2);
        s2 += __shfl_xor_sync(0xffffffffu, s2, 1);
        s2 += __shfl_xor_sync(0xffffffffu, s2, 2);
        const float mean = s1 * (1.f / 256.f);
        const float var  = s2 * (1.f / 256.f) - mean * mean;
        const float rstd = rsqrtf(var + 1e-5f);
        const int p = p0 + wid * 16 + hf * 8 + g;
#pragma unroll
        for (int nb = 0; nb < 32; ++nb)
#pragma unroll
            for (int i2 = 0; i2 < 2; ++i2) {
                const int c = nb * 8 + tig * 2 + i2;
                out[((size_t)b * CH + c) * NPIX + p] =
                    (oacc[nb][hf * 2 + i2] - mean) * rstd * lnw[c] + lnb[c];
            }
    }
}

// ---------------------------------------------------------------------------
extern "C" void kernel_launch(void* const* d_in, const int* in_sizes, int n_in,
                              void* d_out, int out_size)
{
    const float* x1  = (const float*)d_in[0];
    const float* x2  = (const float*)d_in[1];
    const float* qw  = (const float*)d_in[2];
    const float* qb  = (const float*)d_in[3];
    const float* kw  = (const float*)d_in[4];
    const float* kb  = (const float*)d_in[5];
    const float* vw  = (const float*)d_in[6];
    const float* vb  = (const float*)d_in[7];
    const float* lnw = (const float*)d_in[8];
    const float* lnb = (const float*)d_in[9];
    float* out = (float*)d_out;

    splitx_kernel<<<dim3(NPIX / 32, CH / 32, 2 * BATCH), dim3(32, 8)>>>(x1, x2);
    splitw_kernel<<<3 * CH * CH / 512, 512>>>(qw, kw, vw);

    cudaFuncSetAttribute(projmma_kernel, cudaFuncAttributeMaxDynamicSharedMemorySize, PSM_TOT);
    projmma_kernel<<<dim3(NPIX / 128, 3, BATCH), NT, PSM_TOT>>>(qb, kb, vb);

    cudaFuncSetAttribute(attn_kernel, cudaFuncAttributeMaxDynamicSharedMemorySize, SM_TOT);
    attn_kernel<<<dim3(NPIX / TQ, BATCH), NT_A, SM_TOT>>>(lnw, lnb, out);
}

// round 16
// speedup vs baseline: 1.2128x; 1.2128x over previous
#include <cuda_runtime.h>
#include <cuda_fp16.h>
#include <cstdint>

#define BATCH 4
#define CH    256
#define NPIX  4096
#define TQ    128
#define TJ    64
#define NTILE (NPIX / TJ)
#define NT_A  256
#define NT    512

// attention operands (written by proj kernels)
__device__ __align__(128) __half g_Qh[(size_t)BATCH * NPIX * CH];
__device__ __align__(128) __half g_Ql[(size_t)BATCH * NPIX * CH];
__device__ __align__(128) __half g_Kh[(size_t)BATCH * NPIX * CH];
__device__ __align__(128) __half g_Kl[(size_t)BATCH * NPIX * CH];
__device__ __align__(128) __half g_V [(size_t)BATCH * CH * NPIX];   // channel-major fp16

// split inputs for the tensor-core projections
__device__ __align__(128) __half g_x1h[(size_t)BATCH * NPIX * CH];
__device__ __align__(128) __half g_x1l[(size_t)BATCH * NPIX * CH];
__device__ __align__(128) __half g_x2h[(size_t)BATCH * NPIX * CH];
__device__ __align__(128) __half g_x2l[(size_t)BATCH * NPIX * CH];
__device__ __align__(128) __half g_wqh[CH * CH], g_wql[CH * CH];
__device__ __align__(128) __half g_wkh[CH * CH], g_wkl[CH * CH];
__device__ __align__(128) __half g_wvh[CH * CH], g_wvl[CH * CH];

// ---- attn smem layout (TQ=128, dedicated regions) ----
#define SM_Q    0           // Qh 128 x 512B
#define SM_QL   65536       // Ql 128 x 512B
#define SM_K    131072      // Kh 64 x 512B ; Kl at +SM_KLO
#define SM_KLO  32768
#define SM_V    196608      // V 256 x 128B
#define SM_TOT  229376

// ---- proj smem layout ----
#define PSM_X0  0
#define PSM_X1  32768
#define PSM_XL  16384
#define PSM_W0  65536
#define PSM_W1  131072
#define PSM_WL  32768
#define PSM_TOT 196608

#define CP16(dst, src) asm volatile("cp.async.cg.shared.global [%0], [%1], 16;" :: "r"(dst), "l"(src))
#define CP_COMMIT()    asm volatile("cp.async.commit_group;")
#define CP_WAIT_N(n)   asm volatile("cp.async.wait_group %0;" :: "n"(n))

__device__ __forceinline__ uint32_t smem_u32(const void* p) {
    uint32_t a;
    asm("{ .reg .u64 t; cvta.to.shared.u64 t, %1; cvt.u32.u64 %0, t; }" : "=r"(a) : "l"(p));
    return a;
}
__device__ __forceinline__ void ldsm4(uint32_t* r, uint32_t addr) {
    asm volatile("ldmatrix.sync.aligned.m8n8.x4.shared.b16 {%0,%1,%2,%3}, [%4];"
        : "=r"(r[0]), "=r"(r[1]), "=r"(r[2]), "=r"(r[3]) : "r"(addr));
}
__device__ __forceinline__ void mma16816(float* c, const uint32_t* a, uint32_t b0, uint32_t b1) {
    asm volatile(
        "mma.sync.aligned.m16n8k16.row.col.f32.f16.f16.f32 "
        "{%0,%1,%2,%3}, {%4,%5,%6,%7}, {%8,%9}, {%0,%1,%2,%3};"
        : "+f"(c[0]), "+f"(c[1]), "+f"(c[2]), "+f"(c[3])
        : "r"(a[0]), "r"(a[1]), "r"(a[2]), "r"(a[3]), "r"(b0), "r"(b1));
}
__device__ __forceinline__ uint32_t pack_h(__half a, __half b) {
    uint16_t ra = __half_as_ushort(a), rb = __half_as_ushort(b);
    return (uint32_t)ra | ((uint32_t)rb << 16);
}
__device__ __forceinline__ uint32_t packf2(float a, float b) {
    __half2 h = __float22half2_rn(make_float2(a, b));
    return *(uint32_t*)&h;
}
__device__ __forceinline__ void hsplit(float v, __half& h, __half& l) {
    h = __float2half_rn(v);
    l = __float2half_rn(v - __half2float(h));
}

// ---------------------------------------------------------------------------
// split + transpose: both x1 and x2 in one launch (blockIdx.z selects)
// ---------------------------------------------------------------------------
__global__ __launch_bounds__(256) void splitx_kernel(
    const float* __restrict__ x1, const float* __restrict__ x2)
{
    __shared__ float tile[32][33];
    const int which = blockIdx.z >= BATCH ? 1 : 0;
    const int b = blockIdx.z - which * BATCH;
    const float* x = which ? x2 : x1;
    __half* xh = which ? g_x2h : g_x1h;
    __half* xl = which ? g_x2l : g_x1l;
    const int c0 = blockIdx.y * 32, p0 = blockIdx.x * 32;
    const int tx = threadIdx.x, ty = threadIdx.y;

    const float* xb = x + ((size_t)b * CH + c0) * NPIX + p0;
#pragma unroll
    for (int i = 0; i < 4; ++i)
        tile[ty + 8 * i][tx] = xb[(size_t)(ty + 8 * i) * NPIX + tx];
    __syncthreads();

    __half* oh = xh + ((size_t)b * NPIX + p0) * CH + c0;
    __half* ol = xl + ((size_t)b * NPIX + p0) * CH + c0;
#pragma unroll
    for (int i = 0; i < 4; ++i) {
        float v = tile[tx][ty + 8 * i];
        __half h, l; hsplit(v, h, l);
        oh[(size_t)(ty + 8 * i) * CH + tx] = h;
        ol[(size_t)(ty + 8 * i) * CH + tx] = l;
    }
}

// all three weights in one launch
__global__ __launch_bounds__(512) void splitw_kernel(
    const float* __restrict__ qw, const float* __restrict__ kw,
    const float* __restrict__ vw)
{
    const int per = CH * CH / 512;
    const int which = blockIdx.x / per;
    const int i = (blockIdx.x - which * per) * 512 + threadIdx.x;
    const float* w = (which == 0) ? qw : (which == 1) ? kw : vw;
    __half* wh = (which == 0) ? g_wqh : (which == 1) ? g_wkh : g_wvh;
    __half* wl = (which == 0) ? g_wql : (which == 1) ? g_wkl : g_wvl;
    float v = w[i];
    __half h, l; hsplit(v, h, l);
    wh[i] = h; wl[i] = l;
}

// ---------------------------------------------------------------------------
// Tensor-core projection GEMM — Q/K/V in ONE launch (which = blockIdx.y).
// ---------------------------------------------------------------------------
__device__ __forceinline__ void proj_load_chunk(
    uint32_t sb, uint32_t xoff, uint32_t woff, int cc, int t,
    const __half* xb, const __half* xlb, const __half* wh, const __half* wl)
{
    const int c0 = cc * 64;
#pragma unroll
    for (int i = 0; i < 2; ++i) {
        int idx = t + NT * i;
        int row = idx >> 3, c8 = idx & 7;
        uint32_t off = (uint32_t)row * 128u + (uint32_t)((c8 ^ (row & 7)) << 4);
        CP16(sb + xoff + off,          xb  + (size_t)row * CH + c0 + c8 * 8);
        CP16(sb + xoff + PSM_XL + off, xlb + (size_t)row * CH + c0 + c8 * 8);
    }
#pragma unroll
    for (int i = 0; i < 4; ++i) {
        int idx = t + NT * i;
        int row = idx >> 3, c8 = idx & 7;
        uint32_t off = (uint32_t)row * 128u + (uint32_t)((c8 ^ (row & 7)) << 4);
        CP16(sb + woff + off,          wh + (size_t)row * CH + c0 + c8 * 8);
        CP16(sb + woff + PSM_WL + off, wl + (size_t)row * CH + c0 + c8 * 8);
    }
}

__global__ __launch_bounds__(NT, 1) void projmma_kernel(
    const float* __restrict__ qb, const float* __restrict__ kb,
    const float* __restrict__ vb)
{
    extern __shared__ char smem[];
    const uint32_t sb = smem_u32(smem);
    const int t = threadIdx.x, lane = t & 31, wid = t >> 5;
    const int which = blockIdx.y;
    const int b = blockIdx.z, p0 = blockIdx.x * 128;
    const int pw = wid & 3, ow = wid >> 2;
    const int g = lane >> 2, tig = lane & 3;
    const uint32_t l15 = (uint32_t)(lane & 15), lhi = (uint32_t)(lane >> 4);

    const float* bias = (which == 0) ? qb : (which == 1) ? kb : vb;
    const __half *xh, *xl, *wh, *wl;
    if (which == 0)      { xh = g_x1h; xl = g_x1l; wh = g_wqh; wl = g_wql; }
    else if (which == 1) { xh = g_x2h; xl = g_x2l; wh = g_wkh; wl = g_wkl; }
    else                 { xh = g_x2h; xl = g_x2l; wh = g_wvh; wl = g_wvl; }

    const __half* xb  = xh + ((size_t)b * NPIX + p0) * CH;
    const __half* xlb = xl + ((size_t)b * NPIX + p0) * CH;

    float oacc[2][8][4];
#pragma unroll
    for (int m = 0; m < 2; ++m)
#pragma unroll
        for (int nb = 0; nb < 8; ++nb)
#pragma unroll
            for (int i = 0; i < 4; ++i) oacc[m][nb][i] = 0.f;

    const uint32_t am7 = l15 & 7u;
    const uint32_t aXrow = ((uint32_t)(pw * 32) + l15) * 128u;
    const uint32_t aWrow = ((uint32_t)(ow * 64) + l15) * 128u;

    proj_load_chunk(sb, PSM_X0, PSM_W0, 0, t, xb, xlb, wh, wl);
    CP_COMMIT();

#pragma unroll 1
    for (int cc = 0; cc < 4; ++cc) {
        __syncthreads();
        if (cc + 1 < 4) {
            proj_load_chunk(sb, (cc + 1) & 1 ? PSM_X1 : PSM_X0,
                            (cc + 1) & 1 ? PSM_W1 : PSM_W0, cc + 1, t, xb, xlb, wh, wl);
            CP_COMMIT();
        }
        if (cc + 1 < 4) CP_WAIT_N(1); else CP_WAIT_N(0);
        __syncthreads();

        const uint32_t aXh = sb + ((cc & 1) ? PSM_X1 : PSM_X0) + aXrow;
        const uint32_t aXl = aXh + PSM_XL;
        const uint32_t aWh = sb + ((cc & 1) ? PSM_W1 : PSM_W0) + aWrow;
        const uint32_t aWl = aWh + PSM_WL;

#pragma unroll
        for (int kk = 0; kk < 4; ++kk) {
            const uint32_t kc = (uint32_t)(kk * 2) + lhi;
            const uint32_t ca = (kc ^ am7) << 4;
            uint32_t Ah[2][4], Al[2][4];
            ldsm4(Ah[0], aXh + ca); ldsm4(Ah[1], aXh + 2048u + ca);
            ldsm4(Al[0], aXl + ca); ldsm4(Al[1], aXl + 2048u + ca);
#pragma unroll
            for (int seg = 0; seg < 4; ++seg) {
                uint32_t Bh[4], Bl[4];
                ldsm4(Bh, aWh + (uint32_t)seg * 2048u + ca);
                ldsm4(Bl, aWl + (uint32_t)seg * 2048u + ca);
#pragma unroll
                for (int m = 0; m < 2; ++m)
#pragma unroll
                    for (int h = 0; h < 2; ++h) {
                        float* c = oacc[m][seg * 2 + h];
                        mma16816(c, Ah[m], Bh[h], Bh[h + 2]);
                        mma16816(c, Al[m], Bh[h], Bh[h + 2]);
                        mma16816(c, Ah[m], Bl[h], Bl[h + 2]);
                    }
            }
        }
    }

    if (which < 2) {
        __half* OH = which ? g_Kh : g_Qh;
        __half* OL = which ? g_Kl : g_Ql;
#pragma unroll
        for (int m = 0; m < 2; ++m) {
            const int p_lo = p0 + pw * 32 + m * 16 + g;
#pragma unroll
            for (int nb = 0; nb < 8; ++nb) {
                const int o = ow * 64 + nb * 8 + 2 * tig;
                const float b0 = bias[o], b1 = bias[o + 1];
                __half h0, l0, h1, l1;
                hsplit(oacc[m][nb][0] + b0, h0, l0);
                hsplit(oacc[m][nb][1] + b1, h1, l1);
                size_t a0 = ((size_t)b * NPIX + p_lo) * CH + o;
                *(uint32_t*)(OH + a0) = pack_h(h0, h1);
                *(uint32_t*)(OL + a0) = pack_h(l0, l1);
                hsplit(oacc[m][nb][2] + b0, h0, l0);
                hsplit(oacc[m][nb][3] + b1, h1, l1);
                size_t a1 = a0 + (size_t)8 * CH;
                *(uint32_t*)(OH + a1) = pack_h(h0, h1);
                *(uint32_t*)(OL + a1) = pack_h(l0, l1);
            }
        }
    } else {
        __syncthreads();
#pragma unroll
        for (int m = 0; m < 2; ++m) {
            const int p_lo = pw * 32 + m * 16 + g;
#pragma unroll
            for (int nb = 0; nb < 8; ++nb) {
                const int o = ow * 64 + nb * 8 + 2 * tig;
                const float b0 = bias[o], b1 = bias[o + 1];
                *(__half*)(smem + o * 272 + p_lo * 2)             = __float2half_rn(oacc[m][nb][0] + b0);
                *(__half*)(smem + (o + 1) * 272 + p_lo * 2)       = __float2half_rn(oacc[m][nb][1] + b1);
                *(__half*)(smem + o * 272 + (p_lo + 8) * 2)       = __float2half_rn(oacc[m][nb][2] + b0);
                *(__half*)(smem + (o + 1) * 272 + (p_lo + 8) * 2) = __float2half_rn(oacc[m][nb][3] + b1);
            }
        }
        __syncthreads();
#pragma unroll
        for (int i = 0; i < 8; ++i) {
            int idx = t + NT * i;
            int o = idx & 255, pg = idx >> 8;
            uint4 v = *(uint4*)(smem + o * 272 + pg * 16);
            *(uint4*)(g_V + ((size_t)b * CH + o) * NPIX + p0 + pg * 8) = v;
        }
    }
}

// ---------------------------------------------------------------------------
// Flash-style mma.sync attention + fused LayerNorm — 256 threads / 8 warps.
// 3 syncs/tile; P in registers; V(t)/K(t+1) hidden under compute.
// ---------------------------------------------------------------------------
__global__ __launch_bounds__(NT_A, 1) void attn_kernel(
    const float* __restrict__ lnw, const float* __restrict__ lnb,
    float* __restrict__ out)
{
    extern __shared__ char smem[];
    const uint32_t sb = smem_u32(smem);
    const int t = threadIdx.x;
    const int lane = t & 31, wid = t >> 5;
    const int b = blockIdx.y;
    const int p0 = blockIdx.x * TQ;
    const int g = lane >> 2, tig = lane & 3;
    const uint32_t l15 = (uint32_t)(lane & 15), lhi = (uint32_t)(lane >> 4);
    const uint32_t m7 = l15 & 7u;

    const __half* khb = g_Kh + (size_t)b * NPIX * CH;
    const __half* klb = g_Kl + (size_t)b * NPIX * CH;
    const __half* vb_ = g_V  + (size_t)b * CH * NPIX;

    // prologue: Q hi/lo + K(0), one commit group
    {
        const __half* qh = g_Qh + ((size_t)b * NPIX + p0) * CH;
        const __half* ql = g_Ql + ((size_t)b * NPIX + p0) * CH;
#pragma unroll
        for (int i = 0; i < 16; ++i) {
            int idx = t + NT_A * i;
            int row = idx >> 5, c = idx & 31;
            uint32_t off = (uint32_t)row * 512u + (uint32_t)((c ^ (row & 7)) << 4);
            CP16(sb + SM_Q  + off, qh + (size_t)row * CH + c * 8);
            CP16(sb + SM_QL + off, ql + (size_t)row * CH + c * 8);
        }
#pragma unroll
        for (int i = 0; i < 8; ++i) {
            int idx = t + NT_A * i;
            int row = idx >> 5, c = idx & 31;
            uint32_t off = (uint32_t)row * 512u + (uint32_t)((c ^ (row & 7)) << 4);
            CP16(sb + SM_K + off,          khb + (size_t)row * CH + c * 8);
            CP16(sb + SM_K + SM_KLO + off, klb + (size_t)row * CH + c * 8);
        }
        CP_COMMIT();
    }

    float oacc[32][4];
#pragma unroll
    for (int nb = 0; nb < 32; ++nb)
#pragma unroll
        for (int i = 0; i < 4; ++i) oacc[nb][i] = 0.f;

    const uint32_t qrow = (uint32_t)(wid * 16) + l15;
    const uint32_t aQh = sb + SM_Q  + qrow * 512u;
    const uint32_t aQl = sb + SM_QL + qrow * 512u;
    const uint32_t qm7 = qrow & 7u;
    const uint32_t aK  = sb + SM_K + l15 * 512u;
    const uint32_t aKl = aK + SM_KLO;
    const uint32_t aV  = sb + SM_V + l15 * 128u;

#pragma unroll 1
    for (int tile = 0; tile < NTILE; ++tile) {
        CP_WAIT_N(0);      // K(t) landed (only pending group at tile top)
        __syncthreads();   // K visible to all; AV(t-1) done -> V region free

        // issue V(t) — lands under S
        {
            const __half* vh = vb_ + (size_t)tile * TJ;
#pragma unroll
            for (int i = 0; i < 8; ++i) {
                int idx = t + NT_A * i;
                int row = idx >> 3, c = idx & 7;
                uint32_t off = (uint32_t)row * 128u + (uint32_t)((c ^ (row & 7)) << 4);
                CP16(sb + SM_V + off, vh + (size_t)row * NPIX + c * 8);
            }
            CP_COMMIT();
        }

        // ---- S = Q K^T (warp tile 16q x 64j; fp16 3-MMA split)
        float sacc[8][4];
#pragma unroll
        for (int nb = 0; nb < 8; ++nb)
#pragma unroll
            for (int i = 0; i < 4; ++i) sacc[nb][i] = 0.f;

#pragma unroll
        for (int k = 0; k < 16; ++k) {
            const uint32_t kc = (uint32_t)(k * 2) + lhi;
            const uint32_t cq = (kc ^ qm7) << 4;
            const uint32_t ck = (kc ^ m7) << 4;
            uint32_t Ah[4], Al[4];
            ldsm4(Ah, aQh + cq);
            ldsm4(Al, aQl + cq);
#pragma unroll
            for (int jb = 0; jb < 4; ++jb) {
                uint32_t Bh[4], Bl[4];
                ldsm4(Bh, aK  + (uint32_t)jb * 8192u + ck);
                ldsm4(Bl, aKl + (uint32_t)jb * 8192u + ck);
#pragma unroll
                for (int h = 0; h < 2; ++h) {
                    float* c = sacc[jb * 2 + h];
                    mma16816(c, Ah, Bh[h], Bh[h + 2]);
                    mma16816(c, Al, Bh[h], Bh[h + 2]);
                    mma16816(c, Ah, Bl[h], Bl[h + 2]);
                }
            }
        }
        __syncthreads();   // all warps done reading K(t)

        // issue K(t+1) — lands under softmax + AV
        if (tile + 1 < NTILE) {
            const __half* kh = khb + (size_t)(tile + 1) * TJ * CH;
            const __half* kl = klb + (size_t)(tile + 1) * TJ * CH;
#pragma unroll
            for (int i = 0; i < 8; ++i) {
                int idx = t + NT_A * i;
                int row = idx >> 5, c = idx & 31;
                uint32_t off = (uint32_t)row * 512u + (uint32_t)((c ^ (row & 7)) << 4);
                CP16(sb + SM_K + off,          kh + (size_t)row * CH + c * 8);
                CP16(sb + SM_K + SM_KLO + off, kl + (size_t)row * CH + c * 8);
            }
            CP_COMMIT();
        }

        // ---- warp-local softmax (rows g and g+8; 64 j live in 4 tig lanes)
        float inv0, inv1;
        {
            float mx0 = -1e30f, mx1 = -1e30f;
#pragma unroll
            for (int nb = 0; nb < 8; ++nb) {
                mx0 = fmaxf(mx0, fmaxf(sacc[nb][0], sacc[nb][1]));
                mx1 = fmaxf(mx1, fmaxf(sacc[nb][2], sacc[nb][3]));
            }
            mx0 = fmaxf(mx0, __shfl_xor_sync(0xffffffffu, mx0, 1));
            mx0 = fmaxf(mx0, __shfl_xor_sync(0xffffffffu, mx0, 2));
            mx1 = fmaxf(mx1, __shfl_xor_sync(0xffffffffu, mx1, 1));
            mx1 = fmaxf(mx1, __shfl_xor_sync(0xffffffffu, mx1, 2));
            float s0 = 0.f, s1 = 0.f;
#pragma unroll
            for (int nb = 0; nb < 8; ++nb) {
                float e0 = __expf(sacc[nb][0] - mx0);
                float e1 = __expf(sacc[nb][1] - mx0);
                float e2 = __expf(sacc[nb][2] - mx1);
                float e3 = __expf(sacc[nb][3] - mx1);
                sacc[nb][0] = e0; sacc[nb][1] = e1;
                sacc[nb][2] = e2; sacc[nb][3] = e3;
                s0 += e0 + e1; s1 += e2 + e3;
            }
            s0 += __shfl_xor_sync(0xffffffffu, s0, 1);
            s0 += __shfl_xor_sync(0xffffffffu, s0, 2);
            s1 += __shfl_xor_sync(0xffffffffu, s1, 1);
            s1 += __shfl_xor_sync(0xffffffffu, s1, 2);
            inv0 = __fdividef(1.f, s0);
            inv1 = __fdividef(1.f, s1);
        }

        // ---- P fragments in registers (paired f16x2 conversions)
        uint32_t pfrag[4][4];
#pragma unroll
        for (int kk = 0; kk < 4; ++kk) {
            pfrag[kk][0] = packf2(sacc[2 * kk][0] * inv0,     sacc[2 * kk][1] * inv0);
            pfrag[kk][1] = packf2(sacc[2 * kk][2] * inv1,     sacc[2 * kk][3] * inv1);
            pfrag[kk][2] = packf2(sacc[2 * kk + 1][0] * inv0, sacc[2 * kk + 1][1] * inv0);
            pfrag[kk][3] = packf2(sacc[2 * kk + 1][2] * inv1, sacc[2 * kk + 1][3] * inv1);
        }

        if (tile + 1 < NTILE) CP_WAIT_N(1); else CP_WAIT_N(0);   // V(t) landed
        __syncthreads();   // V visible to all

        // ---- O += P V (warp tile 16q x 256c; A from registers)
#pragma unroll
        for (int kk = 0; kk < 4; ++kk) {
            const uint32_t cv = (((uint32_t)(kk * 2) + lhi) ^ m7) << 4;
#pragma unroll
            for (int nbp = 0; nbp < 16; ++nbp) {
                uint32_t Bv[4];
                ldsm4(Bv, aV + (uint32_t)nbp * 2048u + cv);
                mma16816(oacc[nbp * 2],     pfrag[kk], Bv[0], Bv[2]);
                mma16816(oacc[nbp * 2 + 1], pfrag[kk], Bv[1], Bv[3]);
            }
        }
    }

    // ---- fused LayerNorm epilogue (warp-local; rows g and g+8), float2 stores
#pragma unroll
    for (int hf = 0; hf < 2; ++hf) {
        float s1 = 0.f, s2 = 0.f;
#pragma unroll
        for (int nb = 0; nb < 32; ++nb) {
            float v0 = oacc[nb][hf * 2], v1 = oacc[nb][hf * 2 + 1];
            s1 += v0 + v1; s2 += v0 * v0 + v1 * v1;
        }
        s1 += __shfl_xor_sync(0xffffffffu, s1, 1);
        s1 += __shfl_xor_sync(0xffffffffu, s1, 2);
        s2 += __shfl_xor_sync(0xffffffffu, s2, 1);
        s2 += __shfl_xor_sync(0xffffffffu, s2, 2);
        const float mean = s1 * (1.f / 256.f);
        const float var  = s2 * (1.f / 256.f) - mean * mean;
        const float rstd = rsqrtf(var + 1e-5f);
        const int p = p0 + wid * 16 + hf * 8 + g;
#pragma unroll
        for (int nb = 0; nb < 32; ++nb) {
            const int c = nb * 8 + tig * 2;
            // channels c and c+1 for query p (adjacent p-index stride is NPIX;
            // adjacent c differs by NPIX floats — pair within p instead):
            float o0 = (oacc[nb][hf * 2]     - mean) * rstd * lnw[c]     + lnb[c];
            float o1 = (oacc[nb][hf * 2 + 1] - mean) * rstd * lnw[c + 1] + lnb[c + 1];
            out[((size_t)b * CH + c)     * NPIX + p] = o0;
            out[((size_t)b * CH + c + 1) * NPIX + p] = o1;
        }
    }
}

// ---------------------------------------------------------------------------
extern "C" void kernel_launch(void* const* d_in, const int* in_sizes, int n_in,
                              void* d_out, int out_size)
{
    const float* x1  = (const float*)d_in[0];
    const float* x2  = (const float*)d_in[1];
    const float* qw  = (const float*)d_in[2];
    const float* qb  = (const float*)d_in[3];
    const float* kw  = (const float*)d_in[4];
    const float* kb  = (const float*)d_in[5];
    const float* vw  = (const float*)d_in[6];
    const float* vb  = (const float*)d_in[7];
    const float* lnw = (const float*)d_in[8];
    const float* lnb = (const float*)d_in[9];
    float* out = (float*)d_out;

    splitx_kernel<<<dim3(NPIX / 32, CH / 32, 2 * BATCH), dim3(32, 8)>>>(x1, x2);
    splitw_kernel<<<3 * CH * CH / 512, 512>>>(qw, kw, vw);

    cudaFuncSetAttribute(projmma_kernel, cudaFuncAttributeMaxDynamicSharedMemorySize, PSM_TOT);
    projmma_kernel<<<dim3(NPIX / 128, 3, BATCH), NT, PSM_TOT>>>(qb, kb, vb);

    cudaFuncSetAttribute(attn_kernel, cudaFuncAttributeMaxDynamicSharedMemorySize, SM_TOT);
    attn_kernel<<<dim3(NPIX / TQ, BATCH), NT_A, SM_TOT>>>(lnw, lnb, out);
}

// round 17
// speedup vs baseline: 1.2314x; 1.0154x over previous
#include <cuda_runtime.h>
#include <cuda_fp16.h>
#include <cstdint>

#define BATCH 4
#define CH    256
#define NPIX  4096
#define TQ    128
#define TJ    64
#define NTILE (NPIX / TJ)
#define NT_A  256
#define NT    512

// attention operands (written by proj kernels)
__device__ __align__(128) __half g_Qh[(size_t)BATCH * NPIX * CH];
__device__ __align__(128) __half g_Ql[(size_t)BATCH * NPIX * CH];
__device__ __align__(128) __half g_Kh[(size_t)BATCH * NPIX * CH];
__device__ __align__(128) __half g_Kl[(size_t)BATCH * NPIX * CH];
__device__ __align__(128) __half g_V [(size_t)BATCH * CH * NPIX];   // channel-major fp16

// split inputs for the tensor-core projections
__device__ __align__(128) __half g_x1h[(size_t)BATCH * NPIX * CH];
__device__ __align__(128) __half g_x1l[(size_t)BATCH * NPIX * CH];
__device__ __align__(128) __half g_x2h[(size_t)BATCH * NPIX * CH];
__device__ __align__(128) __half g_x2l[(size_t)BATCH * NPIX * CH];
__device__ __align__(128) __half g_wqh[CH * CH], g_wql[CH * CH];
__device__ __align__(128) __half g_wkh[CH * CH], g_wkl[CH * CH];
__device__ __align__(128) __half g_wvh[CH * CH], g_wvl[CH * CH];

// ---- attn smem layout (TQ=128, dedicated regions) ----
#define SM_Q    0           // Qh 128 x 512B
#define SM_QL   65536       // Ql 128 x 512B
#define SM_K    131072      // Kh 64 x 512B ; Kl at +SM_KLO
#define SM_KLO  32768
#define SM_V    196608      // V 256 x 128B
#define SM_TOT  229376

// ---- proj smem layout ----
#define PSM_X0  0
#define PSM_X1  32768
#define PSM_XL  16384
#define PSM_W0  65536
#define PSM_W1  131072
#define PSM_WL  32768
#define PSM_TOT 196608

#define CP16(dst, src) asm volatile("cp.async.cg.shared.global [%0], [%1], 16;" :: "r"(dst), "l"(src))
#define CP_COMMIT()    asm volatile("cp.async.commit_group;")
#define CP_WAIT_N(n)   asm volatile("cp.async.wait_group %0;" :: "n"(n))

__device__ __forceinline__ uint32_t smem_u32(const void* p) {
    uint32_t a;
    asm("{ .reg .u64 t; cvta.to.shared.u64 t, %1; cvt.u32.u64 %0, t; }" : "=r"(a) : "l"(p));
    return a;
}
__device__ __forceinline__ void ldsm4(uint32_t* r, uint32_t addr) {
    asm volatile("ldmatrix.sync.aligned.m8n8.x4.shared.b16 {%0,%1,%2,%3}, [%4];"
        : "=r"(r[0]), "=r"(r[1]), "=r"(r[2]), "=r"(r[3]) : "r"(addr));
}
__device__ __forceinline__ void mma16816(float* c, const uint32_t* a, uint32_t b0, uint32_t b1) {
    asm volatile(
        "mma.sync.aligned.m16n8k16.row.col.f32.f16.f16.f32 "
        "{%0,%1,%2,%3}, {%4,%5,%6,%7}, {%8,%9}, {%0,%1,%2,%3};"
        : "+f"(c[0]), "+f"(c[1]), "+f"(c[2]), "+f"(c[3])
        : "r"(a[0]), "r"(a[1]), "r"(a[2]), "r"(a[3]), "r"(b0), "r"(b1));
}
__device__ __forceinline__ uint32_t pack_h(__half a, __half b) {
    uint16_t ra = __half_as_ushort(a), rb = __half_as_ushort(b);
    return (uint32_t)ra | ((uint32_t)rb << 16);
}
__device__ __forceinline__ uint32_t packf2(float a, float b) {
    __half2 h = __float22half2_rn(make_float2(a, b));
    return *(uint32_t*)&h;
}
__device__ __forceinline__ void hsplit(float v, __half& h, __half& l) {
    h = __float2half_rn(v);
    l = __float2half_rn(v - __half2float(h));
}

// ---------------------------------------------------------------------------
// split + transpose: both x1 and x2 in one launch (blockIdx.z selects)
// ---------------------------------------------------------------------------
__global__ __launch_bounds__(256) void splitx_kernel(
    const float* __restrict__ x1, const float* __restrict__ x2)
{
    __shared__ float tile[32][33];
    const int which = blockIdx.z >= BATCH ? 1 : 0;
    const int b = blockIdx.z - which * BATCH;
    const float* x = which ? x2 : x1;
    __half* xh = which ? g_x2h : g_x1h;
    __half* xl = which ? g_x2l : g_x1l;
    const int c0 = blockIdx.y * 32, p0 = blockIdx.x * 32;
    const int tx = threadIdx.x, ty = threadIdx.y;

    const float* xb = x + ((size_t)b * CH + c0) * NPIX + p0;
#pragma unroll
    for (int i = 0; i < 4; ++i)
        tile[ty + 8 * i][tx] = xb[(size_t)(ty + 8 * i) * NPIX + tx];
    __syncthreads();

    __half* oh = xh + ((size_t)b * NPIX + p0) * CH + c0;
    __half* ol = xl + ((size_t)b * NPIX + p0) * CH + c0;
#pragma unroll
    for (int i = 0; i < 4; ++i) {
        float v = tile[tx][ty + 8 * i];
        __half h, l; hsplit(v, h, l);
        oh[(size_t)(ty + 8 * i) * CH + tx] = h;
        ol[(size_t)(ty + 8 * i) * CH + tx] = l;
    }
}

// all three weights in one launch
__global__ __launch_bounds__(512) void splitw_kernel(
    const float* __restrict__ qw, const float* __restrict__ kw,
    const float* __restrict__ vw)
{
    const int per = CH * CH / 512;
    const int which = blockIdx.x / per;
    const int i = (blockIdx.x - which * per) * 512 + threadIdx.x;
    const float* w = (which == 0) ? qw : (which == 1) ? kw : vw;
    __half* wh = (which == 0) ? g_wqh : (which == 1) ? g_wkh : g_wvh;
    __half* wl = (which == 0) ? g_wql : (which == 1) ? g_wkl : g_wvl;
    float v = w[i];
    __half h, l; hsplit(v, h, l);
    wh[i] = h; wl[i] = l;
}

// ---------------------------------------------------------------------------
// Tensor-core projection GEMM — Q/K/V in ONE launch (which = blockIdx.y).
// ---------------------------------------------------------------------------
__device__ __forceinline__ void proj_load_chunk(
    uint32_t sb, uint32_t xoff, uint32_t woff, int cc, int t,
    const __half* xb, const __half* xlb, const __half* wh, const __half* wl)
{
    const int c0 = cc * 64;
#pragma unroll
    for (int i = 0; i < 2; ++i) {
        int idx = t + NT * i;
        int row = idx >> 3, c8 = idx & 7;
        uint32_t off = (uint32_t)row * 128u + (uint32_t)((c8 ^ (row & 7)) << 4);
        CP16(sb + xoff + off,          xb  + (size_t)row * CH + c0 + c8 * 8);
        CP16(sb + xoff + PSM_XL + off, xlb + (size_t)row * CH + c0 + c8 * 8);
    }
#pragma unroll
    for (int i = 0; i < 4; ++i) {
        int idx = t + NT * i;
        int row = idx >> 3, c8 = idx & 7;
        uint32_t off = (uint32_t)row * 128u + (uint32_t)((c8 ^ (row & 7)) << 4);
        CP16(sb + woff + off,          wh + (size_t)row * CH + c0 + c8 * 8);
        CP16(sb + woff + PSM_WL + off, wl + (size_t)row * CH + c0 + c8 * 8);
    }
}

__global__ __launch_bounds__(NT, 1) void projmma_kernel(
    const float* __restrict__ qb, const float* __restrict__ kb,
    const float* __restrict__ vb)
{
    extern __shared__ char smem[];
    const uint32_t sb = smem_u32(smem);
    const int t = threadIdx.x, lane = t & 31, wid = t >> 5;
    const int which = blockIdx.y;
    const int b = blockIdx.z, p0 = blockIdx.x * 128;
    const int pw = wid & 3, ow = wid >> 2;
    const int g = lane >> 2, tig = lane & 3;
    const uint32_t l15 = (uint32_t)(lane & 15), lhi = (uint32_t)(lane >> 4);

    const float* bias = (which == 0) ? qb : (which == 1) ? kb : vb;
    const __half *xh, *xl, *wh, *wl;
    if (which == 0)      { xh = g_x1h; xl = g_x1l; wh = g_wqh; wl = g_wql; }
    else if (which == 1) { xh = g_x2h; xl = g_x2l; wh = g_wkh; wl = g_wkl; }
    else                 { xh = g_x2h; xl = g_x2l; wh = g_wvh; wl = g_wvl; }

    const __half* xb  = xh + ((size_t)b * NPIX + p0) * CH;
    const __half* xlb = xl + ((size_t)b * NPIX + p0) * CH;

    float oacc[2][8][4];
#pragma unroll
    for (int m = 0; m < 2; ++m)
#pragma unroll
        for (int nb = 0; nb < 8; ++nb)
#pragma unroll
            for (int i = 0; i < 4; ++i) oacc[m][nb][i] = 0.f;

    const uint32_t am7 = l15 & 7u;
    const uint32_t aXrow = ((uint32_t)(pw * 32) + l15) * 128u;
    const uint32_t aWrow = ((uint32_t)(ow * 64) + l15) * 128u;

    proj_load_chunk(sb, PSM_X0, PSM_W0, 0, t, xb, xlb, wh, wl);
    CP_COMMIT();

#pragma unroll 1
    for (int cc = 0; cc < 4; ++cc) {
        __syncthreads();
        if (cc + 1 < 4) {
            proj_load_chunk(sb, (cc + 1) & 1 ? PSM_X1 : PSM_X0,
                            (cc + 1) & 1 ? PSM_W1 : PSM_W0, cc + 1, t, xb, xlb, wh, wl);
            CP_COMMIT();
        }
        if (cc + 1 < 4) CP_WAIT_N(1); else CP_WAIT_N(0);
        __syncthreads();

        const uint32_t aXh = sb + ((cc & 1) ? PSM_X1 : PSM_X0) + aXrow;
        const uint32_t aXl = aXh + PSM_XL;
        const uint32_t aWh = sb + ((cc & 1) ? PSM_W1 : PSM_W0) + aWrow;
        const uint32_t aWl = aWh + PSM_WL;

#pragma unroll
        for (int kk = 0; kk < 4; ++kk) {
            const uint32_t kc = (uint32_t)(kk * 2) + lhi;
            const uint32_t ca = (kc ^ am7) << 4;
            uint32_t Ah[2][4], Al[2][4];
            ldsm4(Ah[0], aXh + ca); ldsm4(Ah[1], aXh + 2048u + ca);
            ldsm4(Al[0], aXl + ca); ldsm4(Al[1], aXl + 2048u + ca);
#pragma unroll
            for (int seg = 0; seg < 4; ++seg) {
                uint32_t Bh[4], Bl[4];
                ldsm4(Bh, aWh + (uint32_t)seg * 2048u + ca);
                ldsm4(Bl, aWl + (uint32_t)seg * 2048u + ca);
#pragma unroll
                for (int m = 0; m < 2; ++m) {
                    float* c0 = oacc[m][seg * 2];
                    float* c1 = oacc[m][seg * 2 + 1];
                    mma16816(c0, Ah[m], Bh[0], Bh[2]);
                    mma16816(c1, Ah[m], Bh[1], Bh[3]);
                    mma16816(c0, Al[m], Bh[0], Bh[2]);
                    mma16816(c1, Al[m], Bh[1], Bh[3]);
                    mma16816(c0, Ah[m], Bl[0], Bl[2]);
                    mma16816(c1, Ah[m], Bl[1], Bl[3]);
                }
            }
        }
    }

    if (which < 2) {
        __half* OH = which ? g_Kh : g_Qh;
        __half* OL = which ? g_Kl : g_Ql;
#pragma unroll
        for (int m = 0; m < 2; ++m) {
            const int p_lo = p0 + pw * 32 + m * 16 + g;
#pragma unroll
            for (int nb = 0; nb < 8; ++nb) {
                const int o = ow * 64 + nb * 8 + 2 * tig;
                const float b0 = bias[o], b1 = bias[o + 1];
                __half h0, l0, h1, l1;
                hsplit(oacc[m][nb][0] + b0, h0, l0);
                hsplit(oacc[m][nb][1] + b1, h1, l1);
                size_t a0 = ((size_t)b * NPIX + p_lo) * CH + o;
                *(uint32_t*)(OH + a0) = pack_h(h0, h1);
                *(uint32_t*)(OL + a0) = pack_h(l0, l1);
                hsplit(oacc[m][nb][2] + b0, h0, l0);
                hsplit(oacc[m][nb][3] + b1, h1, l1);
                size_t a1 = a0 + (size_t)8 * CH;
                *(uint32_t*)(OH + a1) = pack_h(h0, h1);
                *(uint32_t*)(OL + a1) = pack_h(l0, l1);
            }
        }
    } else {
        __syncthreads();
#pragma unroll
        for (int m = 0; m < 2; ++m) {
            const int p_lo = pw * 32 + m * 16 + g;
#pragma unroll
            for (int nb = 0; nb < 8; ++nb) {
                const int o = ow * 64 + nb * 8 + 2 * tig;
                const float b0 = bias[o], b1 = bias[o + 1];
                *(__half*)(smem + o * 272 + p_lo * 2)             = __float2half_rn(oacc[m][nb][0] + b0);
                *(__half*)(smem + (o + 1) * 272 + p_lo * 2)       = __float2half_rn(oacc[m][nb][1] + b1);
                *(__half*)(smem + o * 272 + (p_lo + 8) * 2)       = __float2half_rn(oacc[m][nb][2] + b0);
                *(__half*)(smem + (o + 1) * 272 + (p_lo + 8) * 2) = __float2half_rn(oacc[m][nb][3] + b1);
            }
        }
        __syncthreads();
#pragma unroll
        for (int i = 0; i < 8; ++i) {
            int idx = t + NT * i;
            int o = idx & 255, pg = idx >> 8;
            uint4 v = *(uint4*)(smem + o * 272 + pg * 16);
            *(uint4*)(g_V + ((size_t)b * CH + o) * NPIX + p0 + pg * 8) = v;
        }
    }
}

// ---------------------------------------------------------------------------
// Flash-style mma.sync attention + fused LayerNorm — 256 threads / 8 warps.
// 2 syncs/tile (merged post-S + V-visible); P in registers; loads hidden.
// ---------------------------------------------------------------------------
__global__ __launch_bounds__(NT_A, 1) void attn_kernel(
    const float* __restrict__ lnw, const float* __restrict__ lnb,
    float* __restrict__ out)
{
    extern __shared__ char smem[];
    const uint32_t sb = smem_u32(smem);
    const int t = threadIdx.x;
    const int lane = t & 31, wid = t >> 5;
    const int b = blockIdx.y;
    const int p0 = blockIdx.x * TQ;
    const int g = lane >> 2, tig = lane & 3;
    const uint32_t l15 = (uint32_t)(lane & 15), lhi = (uint32_t)(lane >> 4);
    const uint32_t m7 = l15 & 7u;

    const __half* khb = g_Kh + (size_t)b * NPIX * CH;
    const __half* klb = g_Kl + (size_t)b * NPIX * CH;
    const __half* vb_ = g_V  + (size_t)b * CH * NPIX;

    // prologue: Q hi/lo + K(0), one commit group
    {
        const __half* qh = g_Qh + ((size_t)b * NPIX + p0) * CH;
        const __half* ql = g_Ql + ((size_t)b * NPIX + p0) * CH;
#pragma unroll
        for (int i = 0; i < 16; ++i) {
            int idx = t + NT_A * i;
            int row = idx >> 5, c = idx & 31;
            uint32_t off = (uint32_t)row * 512u + (uint32_t)((c ^ (row & 7)) << 4);
            CP16(sb + SM_Q  + off, qh + (size_t)row * CH + c * 8);
            CP16(sb + SM_QL + off, ql + (size_t)row * CH + c * 8);
        }
#pragma unroll
        for (int i = 0; i < 8; ++i) {
            int idx = t + NT_A * i;
            int row = idx >> 5, c = idx & 31;
            uint32_t off = (uint32_t)row * 512u + (uint32_t)((c ^ (row & 7)) << 4);
            CP16(sb + SM_K + off,          khb + (size_t)row * CH + c * 8);
            CP16(sb + SM_K + SM_KLO + off, klb + (size_t)row * CH + c * 8);
        }
        CP_COMMIT();
    }

    float oacc[32][4];
#pragma unroll
    for (int nb = 0; nb < 32; ++nb)
#pragma unroll
        for (int i = 0; i < 4; ++i) oacc[nb][i] = 0.f;

    const uint32_t qrow = (uint32_t)(wid * 16) + l15;
    const uint32_t aQh = sb + SM_Q  + qrow * 512u;
    const uint32_t aQl = sb + SM_QL + qrow * 512u;
    const uint32_t qm7 = qrow & 7u;
    const uint32_t aK  = sb + SM_K + l15 * 512u;
    const uint32_t aKl = aK + SM_KLO;
    const uint32_t aV  = sb + SM_V + l15 * 128u;

#pragma unroll 1
    for (int tile = 0; tile < NTILE; ++tile) {
        CP_WAIT_N(0);      // K(t) landed (only my pending group at tile top)
        __syncthreads();   // K visible to all; AV(t-1) done -> V region free

        // issue V(t) — lands under S + softmax
        {
            const __half* vh = vb_ + (size_t)tile * TJ;
#pragma unroll
            for (int i = 0; i < 8; ++i) {
                int idx = t + NT_A * i;
                int row = idx >> 3, c = idx & 7;
                uint32_t off = (uint32_t)row * 128u + (uint32_t)((c ^ (row & 7)) << 4);
                CP16(sb + SM_V + off, vh + (size_t)row * NPIX + c * 8);
            }
            CP_COMMIT();
        }

        // ---- S = Q K^T (warp tile 16q x 64j; fp16 3-MMA split, chains interleaved)
        float sacc[8][4];
#pragma unroll
        for (int nb = 0; nb < 8; ++nb)
#pragma unroll
            for (int i = 0; i < 4; ++i) sacc[nb][i] = 0.f;

#pragma unroll
        for (int k = 0; k < 16; ++k) {
            const uint32_t kc = (uint32_t)(k * 2) + lhi;
            const uint32_t cq = (kc ^ qm7) << 4;
            const uint32_t ck = (kc ^ m7) << 4;
            uint32_t Ah[4], Al[4];
            ldsm4(Ah, aQh + cq);
            ldsm4(Al, aQl + cq);
#pragma unroll
            for (int jb = 0; jb < 4; ++jb) {
                uint32_t Bh[4], Bl[4];
                ldsm4(Bh, aK  + (uint32_t)jb * 8192u + ck);
                ldsm4(Bl, aKl + (uint32_t)jb * 8192u + ck);
                float* c0 = sacc[jb * 2];
                float* c1 = sacc[jb * 2 + 1];
                mma16816(c0, Ah, Bh[0], Bh[2]);
                mma16816(c1, Ah, Bh[1], Bh[3]);
                mma16816(c0, Al, Bh[0], Bh[2]);
                mma16816(c1, Al, Bh[1], Bh[3]);
                mma16816(c0, Ah, Bl[0], Bl[2]);
                mma16816(c1, Ah, Bl[1], Bl[3]);
            }
        }

        // ---- warp-local softmax (rows g and g+8; 64 j live in 4 tig lanes)
        float inv0, inv1;
        {
            float mx0 = -1e30f, mx1 = -1e30f;
#pragma unroll
            for (int nb = 0; nb < 8; ++nb) {
                mx0 = fmaxf(mx0, fmaxf(sacc[nb][0], sacc[nb][1]));
                mx1 = fmaxf(mx1, fmaxf(sacc[nb][2], sacc[nb][3]));
            }
            mx0 = fmaxf(mx0, __shfl_xor_sync(0xffffffffu, mx0, 1));
            mx0 = fmaxf(mx0, __shfl_xor_sync(0xffffffffu, mx0, 2));
            mx1 = fmaxf(mx1, __shfl_xor_sync(0xffffffffu, mx1, 1));
            mx1 = fmaxf(mx1, __shfl_xor_sync(0xffffffffu, mx1, 2));
            float s0 = 0.f, s1 = 0.f;
#pragma unroll
            for (int nb = 0; nb < 8; ++nb) {
                float e0 = __expf(sacc[nb][0] - mx0);
                float e1 = __expf(sacc[nb][1] - mx0);
                float e2 = __expf(sacc[nb][2] - mx1);
                float e3 = __expf(sacc[nb][3] - mx1);
                sacc[nb][0] = e0; sacc[nb][1] = e1;
                sacc[nb][2] = e2; sacc[nb][3] = e3;
                s0 += e0 + e1; s1 += e2 + e3;
            }
            s0 += __shfl_xor_sync(0xffffffffu, s0, 1);
            s0 += __shfl_xor_sync(0xffffffffu, s0, 2);
            s1 += __shfl_xor_sync(0xffffffffu, s1, 1);
            s1 += __shfl_xor_sync(0xffffffffu, s1, 2);
            inv0 = __fdividef(1.f, s0);
            inv1 = __fdividef(1.f, s1);
        }

        // ---- P fragments in registers (paired f16x2 conversions)
        uint32_t pfrag[4][4];
#pragma unroll
        for (int kk = 0; kk < 4; ++kk) {
            pfrag[kk][0] = packf2(sacc[2 * kk][0] * inv0,     sacc[2 * kk][1] * inv0);
            pfrag[kk][1] = packf2(sacc[2 * kk][2] * inv1,     sacc[2 * kk][3] * inv1);
            pfrag[kk][2] = packf2(sacc[2 * kk + 1][0] * inv0, sacc[2 * kk + 1][1] * inv0);
            pfrag[kk][3] = packf2(sacc[2 * kk + 1][2] * inv1, sacc[2 * kk + 1][3] * inv1);
        }

        CP_WAIT_N(0);      // V(t) landed (my only pending group)
        __syncthreads();   // MERGED: V visible to all AND all warps past S -> K free

        // issue K(t+1) — lands under AV
        if (tile + 1 < NTILE) {
            const __half* kh = khb + (size_t)(tile + 1) * TJ * CH;
            const __half* kl = klb + (size_t)(tile + 1) * TJ * CH;
#pragma unroll
            for (int i = 0; i < 8; ++i) {
                int idx = t + NT_A * i;
                int row = idx >> 5, c = idx & 31;
                uint32_t off = (uint32_t)row * 512u + (uint32_t)((c ^ (row & 7)) << 4);
                CP16(sb + SM_K + off,          kh + (size_t)row * CH + c * 8);
                CP16(sb + SM_K + SM_KLO + off, kl + (size_t)row * CH + c * 8);
            }
            CP_COMMIT();
        }

        // ---- O += P V (warp tile 16q x 256c; A from registers)
#pragma unroll
        for (int kk = 0; kk < 4; ++kk) {
            const uint32_t cv = (((uint32_t)(kk * 2) + lhi) ^ m7) << 4;
#pragma unroll
            for (int nbp = 0; nbp < 16; ++nbp) {
                uint32_t Bv[4];
                ldsm4(Bv, aV + (uint32_t)nbp * 2048u + cv);
                mma16816(oacc[nbp * 2],     pfrag[kk], Bv[0], Bv[2]);
                mma16816(oacc[nbp * 2 + 1], pfrag[kk], Bv[1], Bv[3]);
            }
        }
    }

    // ---- fused LayerNorm epilogue (warp-local; rows g and g+8)
#pragma unroll
    for (int hf = 0; hf < 2; ++hf) {
        float s1 = 0.f, s2 = 0.f;
#pragma unroll
        for (int nb = 0; nb < 32; ++nb) {
            float v0 = oacc[nb][hf * 2], v1 = oacc[nb][hf * 2 + 1];
            s1 += v0 + v1; s2 += v0 * v0 + v1 * v1;
        }
        s1 += __shfl_xor_sync(0xffffffffu, s1, 1);
        s1 += __shfl_xor_sync(0xffffffffu, s1, 2);
        s2 += __shfl_xor_sync(0xffffffffu, s2, 1);
        s2 += __shfl_xor_sync(0xffffffffu, s2, 2);
        const float mean = s1 * (1.f / 256.f);
        const float var  = s2 * (1.f / 256.f) - mean * mean;
        const float rstd = rsqrtf(var + 1e-5f);
        const int p = p0 + wid * 16 + hf * 8 + g;
#pragma unroll
        for (int nb = 0; nb < 32; ++nb) {
            const int c = nb * 8 + tig * 2;
            float o0 = (oacc[nb][hf * 2]     - mean) * rstd * lnw[c]     + lnb[c];
            float o1 = (oacc[nb][hf * 2 + 1] - mean) * rstd * lnw[c + 1] + lnb[c + 1];
            out[((size_t)b * CH + c)     * NPIX + p] = o0;
            out[((size_t)b * CH + c + 1) * NPIX + p] = o1;
        }
    }
}

// ---------------------------------------------------------------------------
extern "C" void kernel_launch(void* const* d_in, const int* in_sizes, int n_in,
                              void* d_out, int out_size)
{
    const float* x1  = (const float*)d_in[0];
    const float* x2  = (const float*)d_in[1];
    const float* qw  = (const float*)d_in[2];
    const float* qb  = (const float*)d_in[3];
    const float* kw  = (const float*)d_in[4];
    const float* kb  = (const float*)d_in[5];
    const float* vw  = (const float*)d_in[6];
    const float* vb  = (const float*)d_in[7];
    const float* lnw = (const float*)d_in[8];
    const float* lnb = (const float*)d_in[9];
    float* out = (float*)d_out;

    splitx_kernel<<<dim3(NPIX / 32, CH / 32, 2 * BATCH), dim3(32, 8)>>>(x1, x2);
    splitw_kernel<<<3 * CH * CH / 512, 512>>>(qw, kw, vw);

    cudaFuncSetAttribute(projmma_kernel, cudaFuncAttributeMaxDynamicSharedMemorySize, PSM_TOT);
    projmma_kernel<<<dim3(NPIX / 128, 3, BATCH), NT, PSM_TOT>>>(qb, kb, vb);

    cudaFuncSetAttribute(attn_kernel, cudaFuncAttributeMaxDynamicSharedMemorySize, SM_TOT);
    attn_kernel<<<dim3(NPIX / TQ, BATCH), NT_A, SM_TOT>>>(lnw, lnb, out);
}